// round 13
// baseline (speedup 1.0000x reference)
#include <cuda_runtime.h>
#include <math.h>
#include <string.h>

#define BATCH  64
#define TSTEPS 512
#define DIN    512
#define DH     1024

typedef unsigned long long ull;

// ---------------- small helpers ----------------
__device__ __forceinline__ ull f2u(float2 v) { ull r; memcpy(&r, &v, 8); return r; }
__device__ __forceinline__ float2 u2f(ull v) { float2 r; memcpy(&r, &v, 8); return r; }
__device__ __forceinline__ void fma2(ull& acc, ull a, ull b) {
    asm("fma.rn.f32x2 %0, %1, %2, %0;" : "+l"(acc) : "l"(a), "l"(b));
}
__device__ __forceinline__ ull ld_acq(const ull* p) {
    ull v;
    asm volatile("ld.acquire.gpu.global.u64 %0, [%1];" : "=l"(v) : "l"(p) : "memory");
    return v;
}
__device__ __forceinline__ void red_rel_add(ull* p, ull v) {
    asm volatile("red.release.gpu.global.add.u64 [%0], %1;" :: "l"(p), "l"(v) : "memory");
}
__device__ __forceinline__ unsigned s2u(const void* p) {
    unsigned a;
    asm("{ .reg .u64 t; cvta.to.shared.u64 t, %1; cvt.u32.u64 %0, t; }" : "=r"(a) : "l"(p));
    return a;
}
__device__ __forceinline__ void cp_async16(unsigned dst, const void* src) {
    asm volatile("cp.async.cg.shared.global [%0], [%1], 16;" :: "r"(dst), "l"(src) : "memory");
}
__device__ __forceinline__ void cp_commit() {
    asm volatile("cp.async.commit_group;" ::: "memory");
}
template <int N>
__device__ __forceinline__ void cp_wait() {
    asm volatile("cp.async.wait_group %0;" :: "n"(N) : "memory");
}

// ---------------- global scratch + flags (replay-safe) ----------------
__device__ float g_Wt[DH * DIN];     // W transposed: [j][k], 2 MB
__device__ ull   g_flags[2][16];     // monotonic dataflow flags

// ---------------- W transpose kernel (runs once, ~20 us) ----------------
__global__ __launch_bounds__(256) void transpose_W(const float* __restrict__ W)
{
    __shared__ float tile[32][33];
    const int jBase = blockIdx.x * 32;
    const int kBase = blockIdx.y * 32;
    const int tx = threadIdx.x, ty = threadIdx.y;   // 32 x 8
#pragma unroll
    for (int p = 0; p < 4; ++p)
        tile[ty + 8 * p][tx] = W[(size_t)(kBase + ty + 8 * p) * DH + jBase + tx];
    __syncthreads();
#pragma unroll
    for (int p = 0; p < 4; ++p)
        g_Wt[(size_t)(jBase + ty + 8 * p) * DIN + kBase + tx] = tile[tx][ty + 8 * p];
}

// ---------------- fused persistent kernel ----------------
// 128 blocks: gm = bid>>6 (m-tile 32), gn = bid&63 (j-tile 16). 16 warps.
// Phase B (top of step, before poll): preact(t+2) = x.W + b for own tile.
//   Warp w owns preact-k [32w,+32); x and Wt (both k-contiguous) from L2 via
//   __ldg -> packing-free f32x2. Same P slots + reduce as phase A.
// Phase A: r10 skeleton exactly (flag poll all-lane, cp.async h staging in
//   2 overlapped halves, f32x2 broadcast 4x4 micro-tile, conflict-free P).
#define TPB 512
#define HSTRIDE 1028
#define H_OFF 0
#define R_OFF (32 * HSTRIDE)                  // 32896
#define P_OFF (R_OFF + 16 * HSTRIDE)          // 49344
#define SMEM_FLOATS (P_OFF + 16 * 512)        // 57536 floats = 230144 B

__global__ __launch_bounds__(TPB, 1)
void rnn_fused_kernel(const float* __restrict__ x,
                      const float* __restrict__ h0,
                      const float* __restrict__ R,
                      const float* __restrict__ bias,
                      float* out)
{
    extern __shared__ float S[];

    const int tid    = threadIdx.x;
    const int w      = tid >> 5;
    const int lane   = tid & 31;
    const int m_lane = lane & 7;
    const int j_lane = lane >> 3;
    const int gm     = (int)(blockIdx.x >> 6);
    const int gn     = (int)(blockIdx.x & 63);
    const int mBase  = gm << 5;
    const int jBase  = gn << 4;

    const ull* myflag = &g_flags[gm][w];
    ull* prodflag     = &g_flags[gm][gn >> 2];

    // snapshot monotonic flag base (all flags equal at kernel entry)
    ull base0 = 0;
    if (lane == 0) base0 = ld_acq(myflag);
    const ull base = __shfl_sync(0xFFFFFFFFu, base0, 0);

    // ---- stage R transposed into smem [j][k] (once) ----
#pragma unroll
    for (int p = 0; p < 8; ++p) {
        int idx = tid + p * TPB;
        int k = idx >> 2, q = idx & 3;
        float4 v = *(const float4*)(R + (size_t)k * DH + jBase + q * 4);
        S[R_OFF + (q * 4 + 0) * HSTRIDE + k] = v.x;
        S[R_OFF + (q * 4 + 1) * HSTRIDE + k] = v.y;
        S[R_OFF + (q * 4 + 2) * HSTRIDE + k] = v.z;
        S[R_OFF + (q * 4 + 3) * HSTRIDE + k] = v.w;
    }
    __syncthreads();

    const float* Hp = S + H_OFF + (size_t)m_lane * HSTRIDE + w * 64;
    const float* Rp = S + R_OFF + (size_t)j_lane * HSTRIDE + w * 64;

    // shared epilogue decode (A and B use the same P slot layout)
    const int sub  = tid >> 5;
    const int m_r  = ((tid & 31) >> 2) + 8 * (sub >> 2);
    const int j_r  = (tid & 3) + 4 * (sub & 3);
    const size_t rowBase = (size_t)(mBase + m_r) * TSTEPS * DH + jBase + j_r;
    const float biasreg = bias[jBase + j_r];

    // phase-A h staging decode
    const int klocA = (lane & 7) * 4;
    const int rbase = lane >> 3;

    // phase-B bases (loop-invariant): x rows and Wt rows
    const int kB = w * 32;
    const float* xrow[4];
#pragma unroll
    for (int mi = 0; mi < 4; ++mi)
        xrow[mi] = x + (size_t)(mBase + m_lane + 8 * mi) * (TSTEPS * DIN) + kB;
    const float* wrow[4];
#pragma unroll
    for (int ji = 0; ji < 4; ++ji)
        wrow[ji] = g_Wt + (size_t)(jBase + j_lane + 4 * ji) * DIN + kB;
    const int lbase = m_lane * 4 + j_lane;

    // ---- phase B body (compute + STS + bar + reduce + STG preact(tau)) ----
#define B_PASS(tau) {                                                        \
        const size_t xoff = (size_t)(tau) * DIN;                             \
        ull accB[4][4];                                                      \
        _Pragma("unroll")                                                    \
        for (int mi = 0; mi < 4; ++mi)                                       \
            _Pragma("unroll")                                                \
            for (int ji = 0; ji < 4; ++ji) accB[mi][ji] = 0ull;              \
        _Pragma("unroll")                                                    \
        for (int it = 0; it < 8; ++it) {                                     \
            const int off = it * 4;                                          \
            float4 xv[4], wv[4];                                             \
            _Pragma("unroll")                                                \
            for (int mi = 0; mi < 4; ++mi)                                   \
                xv[mi] = __ldg((const float4*)(xrow[mi] + xoff + off));      \
            _Pragma("unroll")                                                \
            for (int ji = 0; ji < 4; ++ji)                                   \
                wv[ji] = __ldg((const float4*)(wrow[ji] + off));             \
            _Pragma("unroll")                                                \
            for (int mi = 0; mi < 4; ++mi) {                                 \
                ull xlo = f2u(make_float2(xv[mi].x, xv[mi].y));              \
                ull xhi = f2u(make_float2(xv[mi].z, xv[mi].w));              \
                _Pragma("unroll")                                            \
                for (int ji = 0; ji < 4; ++ji) {                             \
                    fma2(accB[mi][ji], xlo, f2u(make_float2(wv[ji].x, wv[ji].y))); \
                    fma2(accB[mi][ji], xhi, f2u(make_float2(wv[ji].z, wv[ji].w))); \
                }                                                            \
            }                                                                \
        }                                                                    \
        float* Pw = S + P_OFF + w * 512;                                     \
        _Pragma("unroll")                                                    \
        for (int mi = 0; mi < 4; ++mi)                                       \
            _Pragma("unroll")                                                \
            for (int ji = 0; ji < 4; ++ji) {                                 \
                float2 c = u2f(accB[mi][ji]);                                \
                Pw[32 * (mi * 4 + ji) + lbase] = c.x + c.y;                  \
            }                                                                \
        __syncthreads();  /* (c) B-partials visible */                       \
        {                                                                    \
            float s0 = 0.f, s1 = 0.f, s2 = 0.f, s3 = 0.f;                    \
            _Pragma("unroll")                                                \
            for (int q = 0; q < 4; ++q) {                                    \
                s0 += S[P_OFF + (q +  0) * 512 + tid];                       \
                s1 += S[P_OFF + (q +  4) * 512 + tid];                       \
                s2 += S[P_OFF + (q +  8) * 512 + tid];                       \
                s3 += S[P_OFF + (q + 12) * 512 + tid];                       \
            }                                                                \
            out[rowBase + (size_t)(tau) * DH] = biasreg + (s0 + s1) + (s2 + s3); \
        }                                                                    \
        __syncthreads();  /* (d) B-P reads done before next P writes */      \
    }

    // ===================== prologue: preact for tau = 0, 1 ==============
    B_PASS(0)
    B_PASS(1)

    // ===================== main time loop ===============================
#pragma unroll 1
    for (int t = 0; t < TSTEPS; ++t) {
        const int tau = t + 2;

        // ---- prefetch this block's preact for step t (L1-bypass) ----
        const size_t oi = rowBase + (size_t)t * DH;
        const float pre = __ldcg(out + oi);

        // ---- phase B: preact(tau), overlapping producers' step t-1 ----
        if (tau < TSTEPS) { B_PASS(tau) }

        // ---- wait for my chunk's 4 producers to finish step t-1 ----
        if (t > 0) {
            const ull target = base + 4ull * (ull)t;
            while (ld_acq(myflag) < target) { }
        }

        // ---- stage h slice via cp.async in 2 k-half groups ----
        const float* hb;
        size_t rstr;
        if (t == 0) { hb = h0 + (size_t)mBase * DH; rstr = DH; }
        else {
            hb = out + (size_t)(t - 1) * DH + (size_t)mBase * ((size_t)TSTEPS * DH);
            rstr = (size_t)TSTEPS * DH;
        }
#pragma unroll
        for (int g = 0; g < 2; ++g) {
            const int kb = w * 64 + g * 32 + klocA;
#pragma unroll
            for (int p = 0; p < 8; ++p) {
                const int row = rbase + 4 * p;
                cp_async16(s2u(&S[H_OFF + row * HSTRIDE + kb]),
                           hb + (size_t)row * rstr + kb);
            }
            cp_commit();
        }

        ull acc[4][4];
#pragma unroll
        for (int mi = 0; mi < 4; ++mi)
#pragma unroll
            for (int ji = 0; ji < 4; ++ji) acc[mi][ji] = 0ull;

        // ---- compute half 0 while half 1 lands ----
        cp_wait<1>(); __syncwarp();
#pragma unroll
        for (int it = 0; it < 8; ++it) {
            const int off = it * 4;
            float4 h[4], r[4];
#pragma unroll
            for (int mi = 0; mi < 4; ++mi)
                h[mi] = *(const float4*)(Hp + (size_t)(mi * 8) * HSTRIDE + off);
#pragma unroll
            for (int ji = 0; ji < 4; ++ji)
                r[ji] = *(const float4*)(Rp + (size_t)(ji * 4) * HSTRIDE + off);
#pragma unroll
            for (int mi = 0; mi < 4; ++mi) {
                ull hlo = f2u(make_float2(h[mi].x, h[mi].y));
                ull hhi = f2u(make_float2(h[mi].z, h[mi].w));
#pragma unroll
                for (int ji = 0; ji < 4; ++ji) {
                    fma2(acc[mi][ji], hlo, f2u(make_float2(r[ji].x, r[ji].y)));
                    fma2(acc[mi][ji], hhi, f2u(make_float2(r[ji].z, r[ji].w)));
                }
            }
        }

        // ---- compute half 1 ----
        cp_wait<0>(); __syncwarp();
#pragma unroll
        for (int it = 8; it < 16; ++it) {
            const int off = it * 4;
            float4 h[4], r[4];
#pragma unroll
            for (int mi = 0; mi < 4; ++mi)
                h[mi] = *(const float4*)(Hp + (size_t)(mi * 8) * HSTRIDE + off);
#pragma unroll
            for (int ji = 0; ji < 4; ++ji)
                r[ji] = *(const float4*)(Rp + (size_t)(ji * 4) * HSTRIDE + off);
#pragma unroll
            for (int mi = 0; mi < 4; ++mi) {
                ull hlo = f2u(make_float2(h[mi].x, h[mi].y));
                ull hhi = f2u(make_float2(h[mi].z, h[mi].w));
#pragma unroll
                for (int ji = 0; ji < 4; ++ji) {
                    fma2(acc[mi][ji], hlo, f2u(make_float2(r[ji].x, r[ji].y)));
                    fma2(acc[mi][ji], hhi, f2u(make_float2(r[ji].z, r[ji].w)));
                }
            }
        }

        // ---- phase-A partials: conflict-free writes ----
        {
            float* Pw = S + P_OFF + w * 512;
#pragma unroll
            for (int mi = 0; mi < 4; ++mi)
#pragma unroll
                for (int ji = 0; ji < 4; ++ji) {
                    float2 c = u2f(acc[mi][ji]);
                    Pw[32 * (mi * 4 + ji) + lbase] = c.x + c.y;
                }
        }
        __syncthreads();   // (a) A-partials visible

        // ---- reduce 16 partials + preact + tanh + store h_t ----
        {
            float s0 = 0.f, s1 = 0.f, s2 = 0.f, s3 = 0.f;
#pragma unroll
            for (int q = 0; q < 4; ++q) {
                s0 += S[P_OFF + (q +  0) * 512 + tid];
                s1 += S[P_OFF + (q +  4) * 512 + tid];
                s2 += S[P_OFF + (q +  8) * 512 + tid];
                s3 += S[P_OFF + (q + 12) * 512 + tid];
            }
            out[oi] = tanhf(pre + (s0 + s1) + (s2 + s3));
        }

        __syncthreads();   // (b) h stores + A-P reads done (release ordering)

        // ---- announce: this block finished step t ----
        if (tid == 0) red_rel_add(prodflag, 1ull);
    }
#undef B_PASS
}

// ---------------- launch ----------------
extern "C" void kernel_launch(void* const* d_in, const int* in_sizes, int n_in,
                              void* d_out, int out_size)
{
    const float* x  = (const float*)d_in[0];   // [64,512,512]
    const float* h0 = (const float*)d_in[1];   // [64,1024]
    const float* W  = (const float*)d_in[2];   // [512,1024]
    const float* R  = (const float*)d_in[3];   // [1024,1024]
    const float* b  = (const float*)d_in[4];   // [1,1024]
    float* out = (float*)d_out;                // [64,512,1024]

    const int smem_bytes = SMEM_FLOATS * 4;    // 230144 <= 232448
    cudaFuncSetAttribute(rnn_fused_kernel,
                         cudaFuncAttributeMaxDynamicSharedMemorySize, smem_bytes);

    dim3 gT(DH / 32, DIN / 32);                // (32, 16)
    transpose_W<<<gT, dim3(32, 8)>>>(W);

    rnn_fused_kernel<<<128, TPB, smem_bytes>>>(x, h0, R, b, out);
}

// round 14
// speedup vs baseline: 1.9352x; 1.9352x over previous
#include <cuda_runtime.h>
#include <math.h>
#include <string.h>

#define BATCH  64
#define TSTEPS 512
#define DIN    512
#define DH     1024
#define MROWS  (BATCH * TSTEPS)   // 32768

typedef unsigned long long ull;

// ---------------- small helpers ----------------
__device__ __forceinline__ ull f2u(float2 v) { ull r; memcpy(&r, &v, 8); return r; }
__device__ __forceinline__ float2 u2f(ull v) { float2 r; memcpy(&r, &v, 8); return r; }
__device__ __forceinline__ ull pack2(float v) {
    ull r; asm("mov.b64 %0, {%1, %1};" : "=l"(r) : "f"(v)); return r;
}
__device__ __forceinline__ void fma2(ull& acc, ull a, ull b) {
    asm("fma.rn.f32x2 %0, %1, %2, %0;" : "+l"(acc) : "l"(a), "l"(b));
}
__device__ __forceinline__ ull ld_acq(const ull* p) {
    ull v;
    asm volatile("ld.acquire.gpu.global.u64 %0, [%1];" : "=l"(v) : "l"(p) : "memory");
    return v;
}
__device__ __forceinline__ void red_rel_add(ull* p, ull v) {
    asm volatile("red.release.gpu.global.add.u64 [%0], %1;" :: "l"(p), "l"(v) : "memory");
}
__device__ __forceinline__ unsigned s2u(const void* p) {
    unsigned a;
    asm("{ .reg .u64 t; cvta.to.shared.u64 t, %1; cvt.u32.u64 %0, t; }" : "=r"(a) : "l"(p));
    return a;
}
__device__ __forceinline__ void cp_async16(unsigned dst, const void* src) {
    asm volatile("cp.async.cg.shared.global [%0], [%1], 16;" :: "r"(dst), "l"(src) : "memory");
}
__device__ __forceinline__ void cp_commit() {
    asm volatile("cp.async.commit_group;" ::: "memory");
}
template <int N>
__device__ __forceinline__ void cp_wait() {
    asm volatile("cp.async.wait_group %0;" :: "n"(N) : "memory");
}

// ---------------- global scratch + flags (replay-safe) ----------------
__device__ float g_Xt[(size_t)DIN * MROWS];   // X transposed [k][m], 64 MB
__device__ ull   g_flags[2][16];              // monotonic dataflow flags

// ---------------- X transpose kernel (~25 us, runs once per launch) --------
__global__ __launch_bounds__(256) void transpose_X(const float* __restrict__ X)
{
    __shared__ float tile[32][33];
    const int kBase = blockIdx.x * 32;
    const int mBase = blockIdx.y * 32;
    const int tx = threadIdx.x, ty = threadIdx.y;   // 32 x 8
#pragma unroll
    for (int p = 0; p < 4; ++p)
        tile[ty + 8 * p][tx] = X[(size_t)(mBase + ty + 8 * p) * DIN + kBase + tx];
    __syncthreads();
#pragma unroll
    for (int p = 0; p < 4; ++p)
        g_Xt[(size_t)(kBase + ty + 8 * p) * MROWS + mBase + tx] = tile[tx][ty + 8 * p];
}

// ---------------- Kernel A v3: C = x @ W + bias (cp.async double-buffered) -
// 128x128 tile, 256 threads, k-tile 16 double buffered. Both operands are
// k-row-contiguous (g_Xt[k][m], W[k][n]) -> pure cp.async staging, f32x2
// 8x8 micro-tile inner loop (m-paired accumulators).
__global__ __launch_bounds__(256) void gemm_xw_v3(
    const float* __restrict__ W, const float* __restrict__ bias,
    float* __restrict__ C)
{
    __shared__ float As[2][16][132];   // [buf][k][m]
    __shared__ float Bs[2][16][132];   // [buf][k][n]

    const int tid   = threadIdx.x;
    const int tx    = tid & 15;
    const int ty    = tid >> 4;
    const int mBase = blockIdx.y << 7;
    const int nBase = blockIdx.x << 7;

    // staging decode: row r = tid>>4 (0..15), col8 = (tid&15)*8
    const int sr = tid >> 4;
    const int sc = (tid & 15) * 8;

#define STAGE(buf, kt) {                                                     \
        const int k0 = (kt) * 16;                                            \
        const float* aSrc = g_Xt + (size_t)(k0 + sr) * MROWS + mBase + sc;   \
        const float* bSrc = W    + (size_t)(k0 + sr) * DH    + nBase + sc;   \
        cp_async16(s2u(&As[buf][sr][sc]),     aSrc);                         \
        cp_async16(s2u(&As[buf][sr][sc + 4]), aSrc + 4);                     \
        cp_async16(s2u(&Bs[buf][sr][sc]),     bSrc);                         \
        cp_async16(s2u(&Bs[buf][sr][sc + 4]), bSrc + 4);                     \
        cp_commit(); }

    ull acc[4][8];
#pragma unroll
    for (int p = 0; p < 4; ++p)
#pragma unroll
        for (int n = 0; n < 8; ++n) acc[p][n] = 0ull;

    STAGE(0, 0)

#pragma unroll 1
    for (int kt = 0; kt < DIN / 16; ++kt) {
        __syncthreads();                       // prev compute done (WAR for stage)
        if (kt + 1 < DIN / 16) STAGE((kt + 1) & 1, kt + 1)
        cp_wait<1>();                          // tile kt landed
        __syncthreads();                       // visible to all warps
        const int buf = kt & 1;
#pragma unroll
        for (int kk = 0; kk < 16; ++kk) {
            float4 a0 = *(const float4*)&As[buf][kk][ty * 8];
            float4 a1 = *(const float4*)&As[buf][kk][ty * 8 + 4];
            float4 b0 = *(const float4*)&Bs[buf][kk][tx * 8];
            float4 b1 = *(const float4*)&Bs[buf][kk][tx * 8 + 4];
            ull am[4];
            am[0] = f2u(make_float2(a0.x, a0.y));
            am[1] = f2u(make_float2(a0.z, a0.w));
            am[2] = f2u(make_float2(a1.x, a1.y));
            am[3] = f2u(make_float2(a1.z, a1.w));
            ull bn[8];
            bn[0] = pack2(b0.x); bn[1] = pack2(b0.y); bn[2] = pack2(b0.z); bn[3] = pack2(b0.w);
            bn[4] = pack2(b1.x); bn[5] = pack2(b1.y); bn[6] = pack2(b1.z); bn[7] = pack2(b1.w);
#pragma unroll
            for (int p = 0; p < 4; ++p)
#pragma unroll
                for (int n = 0; n < 8; ++n)
                    fma2(acc[p][n], am[p], bn[n]);
        }
    }
#undef STAGE

    float4 bb0 = *(const float4*)(bias + nBase + tx * 8);
    float4 bb1 = *(const float4*)(bias + nBase + tx * 8 + 4);
    float bbs[8] = {bb0.x, bb0.y, bb0.z, bb0.w, bb1.x, bb1.y, bb1.z, bb1.w};

#pragma unroll
    for (int p = 0; p < 4; ++p) {
        float2 c[8];
#pragma unroll
        for (int n = 0; n < 8; ++n) c[n] = u2f(acc[p][n]);
        int row0 = mBase + ty * 8 + p * 2;
        float* out0 = C + (size_t)row0 * DH + nBase + tx * 8;
        float* out1 = out0 + DH;
        float4 o;
        o.x = c[0].x + bbs[0]; o.y = c[1].x + bbs[1]; o.z = c[2].x + bbs[2]; o.w = c[3].x + bbs[3];
        *(float4*)out0 = o;
        o.x = c[4].x + bbs[4]; o.y = c[5].x + bbs[5]; o.z = c[6].x + bbs[6]; o.w = c[7].x + bbs[7];
        *(float4*)(out0 + 4) = o;
        o.x = c[0].y + bbs[0]; o.y = c[1].y + bbs[1]; o.z = c[2].y + bbs[2]; o.w = c[3].y + bbs[3];
        *(float4*)out1 = o;
        o.x = c[4].y + bbs[4]; o.y = c[5].y + bbs[5]; o.z = c[6].y + bbs[6]; o.w = c[7].y + bbs[7];
        *(float4*)(out1 + 4) = o;
    }
}

// ---------------- Kernel B: persistent recurrence (r10, best known) --------
// 128 blocks: gm = bid>>6 (m-tile 32), gn = bid&63 (j-tile 16). 16 warps.
// Warp w owns k-range [64w,+64), waits on flag[gm][w] (producers 4w..4w+3),
// all-lane poll. h staged per warp via cp.async.cg in TWO k-half groups
// (compute half 0 overlaps landing of half 1). R persistent in smem [j][k].
// f32x2 broadcast micro-tile 4x4. Partials: conflict-free layout
// P[w*512 + 32*(mi*4+ji) + m_lane*4 + j_lane]; reduce reads contiguous.
#define TPB 512
#define HSTRIDE 1028
#define H_OFF 0
#define R_OFF (32 * HSTRIDE)                  // 32896
#define P_OFF (R_OFF + 16 * HSTRIDE)          // 49344
#define SMEM_FLOATS (P_OFF + 16 * 512)        // 57536 floats = 230144 B

__global__ __launch_bounds__(TPB, 1)
void rnn_recur_kernel(const float* __restrict__ h0, const float* __restrict__ R, float* out)
{
    extern __shared__ float S[];

    const int tid    = threadIdx.x;
    const int w      = tid >> 5;
    const int lane   = tid & 31;
    const int m_lane = lane & 7;
    const int j_lane = lane >> 3;
    const int gm     = (int)(blockIdx.x >> 6);
    const int gn     = (int)(blockIdx.x & 63);
    const int mBase  = gm << 5;
    const int jBase  = gn << 4;

    const ull* myflag = &g_flags[gm][w];
    ull* prodflag     = &g_flags[gm][gn >> 2];

    // snapshot monotonic flag base (all flags equal at kernel entry)
    ull base0 = 0;
    if (lane == 0) base0 = ld_acq(myflag);
    const ull base = __shfl_sync(0xFFFFFFFFu, base0, 0);

    // ---- stage R transposed into smem [j][k] (once) ----
#pragma unroll
    for (int p = 0; p < 8; ++p) {
        int idx = tid + p * TPB;
        int k = idx >> 2, q = idx & 3;
        float4 v = *(const float4*)(R + (size_t)k * DH + jBase + q * 4);
        S[R_OFF + (q * 4 + 0) * HSTRIDE + k] = v.x;
        S[R_OFF + (q * 4 + 1) * HSTRIDE + k] = v.y;
        S[R_OFF + (q * 4 + 2) * HSTRIDE + k] = v.z;
        S[R_OFF + (q * 4 + 3) * HSTRIDE + k] = v.w;
    }
    __syncthreads();

    const float* Hp = S + H_OFF + (size_t)m_lane * HSTRIDE + w * 64;
    const float* Rp = S + R_OFF + (size_t)j_lane * HSTRIDE + w * 64;

    // epilogue decode: tid -> (m, j) matching conflict-free P layout
    const int sub  = tid >> 5;
    const int mi_r = sub >> 2, ji_r = sub & 3;
    const int m_r  = ((tid & 31) >> 2) + 8 * mi_r;
    const int j_r  = (tid & 3) + 4 * ji_r;

    // staging decode: group g covers k in [w*64 + g*32, +32).
    const int klocal = (lane & 7) * 4;
    const int rbase  = lane >> 3;

#pragma unroll 1
    for (int t = 0; t < TSTEPS; ++t) {
        // ---- prefetch this block's preact (own tile; L1-bypass) ----
        const size_t oi = ((size_t)(mBase + m_r) * TSTEPS + t) * DH + jBase + j_r;
        const float pre = __ldcg(out + oi);

        // ---- wait for my chunk's 4 producers to finish step t-1 ----
        if (t > 0) {
            const ull target = base + 4ull * (ull)t;
            while (ld_acq(myflag) < target) { }
        }

        // ---- stage h slice via cp.async in 2 k-half groups ----
        const float* hb;
        size_t rstr;
        if (t == 0) { hb = h0 + (size_t)mBase * DH; rstr = DH; }
        else {
            hb = out + (size_t)(t - 1) * DH + (size_t)mBase * ((size_t)TSTEPS * DH);
            rstr = (size_t)TSTEPS * DH;
        }
#pragma unroll
        for (int g = 0; g < 2; ++g) {
            const int kb = w * 64 + g * 32 + klocal;
#pragma unroll
            for (int p = 0; p < 8; ++p) {
                const int row = rbase + 4 * p;
                cp_async16(s2u(&S[H_OFF + row * HSTRIDE + kb]),
                           hb + (size_t)row * rstr + kb);
            }
            cp_commit();
        }

        ull acc[4][4];
#pragma unroll
        for (int mi = 0; mi < 4; ++mi)
#pragma unroll
            for (int ji = 0; ji < 4; ++ji) acc[mi][ji] = 0ull;

        // ---- compute half 0 while half 1 lands ----
        cp_wait<1>(); __syncwarp();
#pragma unroll
        for (int it = 0; it < 8; ++it) {
            const int off = it * 4;
            float4 h[4], r[4];
#pragma unroll
            for (int mi = 0; mi < 4; ++mi)
                h[mi] = *(const float4*)(Hp + (size_t)(mi * 8) * HSTRIDE + off);
#pragma unroll
            for (int ji = 0; ji < 4; ++ji)
                r[ji] = *(const float4*)(Rp + (size_t)(ji * 4) * HSTRIDE + off);
#pragma unroll
            for (int mi = 0; mi < 4; ++mi) {
                ull hlo = f2u(make_float2(h[mi].x, h[mi].y));
                ull hhi = f2u(make_float2(h[mi].z, h[mi].w));
#pragma unroll
                for (int ji = 0; ji < 4; ++ji) {
                    fma2(acc[mi][ji], hlo, f2u(make_float2(r[ji].x, r[ji].y)));
                    fma2(acc[mi][ji], hhi, f2u(make_float2(r[ji].z, r[ji].w)));
                }
            }
        }

        // ---- compute half 1 ----
        cp_wait<0>(); __syncwarp();
#pragma unroll
        for (int it = 8; it < 16; ++it) {
            const int off = it * 4;
            float4 h[4], r[4];
#pragma unroll
            for (int mi = 0; mi < 4; ++mi)
                h[mi] = *(const float4*)(Hp + (size_t)(mi * 8) * HSTRIDE + off);
#pragma unroll
            for (int ji = 0; ji < 4; ++ji)
                r[ji] = *(const float4*)(Rp + (size_t)(ji * 4) * HSTRIDE + off);
#pragma unroll
            for (int mi = 0; mi < 4; ++mi) {
                ull hlo = f2u(make_float2(h[mi].x, h[mi].y));
                ull hhi = f2u(make_float2(h[mi].z, h[mi].w));
#pragma unroll
                for (int ji = 0; ji < 4; ++ji) {
                    fma2(acc[mi][ji], hlo, f2u(make_float2(r[ji].x, r[ji].y)));
                    fma2(acc[mi][ji], hhi, f2u(make_float2(r[ji].z, r[ji].w)));
                }
            }
        }

        // ---- partials: conflict-free writes (32 lanes -> 32 banks) ----
        {
            float* Pw = S + P_OFF + w * 512;
            const int lbase = m_lane * 4 + j_lane;
#pragma unroll
            for (int mi = 0; mi < 4; ++mi)
#pragma unroll
                for (int ji = 0; ji < 4; ++ji) {
                    float2 c = u2f(acc[mi][ji]);
                    Pw[32 * (mi * 4 + ji) + lbase] = c.x + c.y;
                }
        }
        __syncthreads();   // (a) partials visible

        // ---- reduce 16 partials (contiguous reads) + tanh + store h_t ----
        {
            float s0 = 0.f, s1 = 0.f, s2 = 0.f, s3 = 0.f;
#pragma unroll
            for (int q = 0; q < 4; ++q) {
                s0 += S[P_OFF + (q +  0) * 512 + tid];
                s1 += S[P_OFF + (q +  4) * 512 + tid];
                s2 += S[P_OFF + (q +  8) * 512 + tid];
                s3 += S[P_OFF + (q + 12) * 512 + tid];
            }
            out[oi] = tanhf(pre + (s0 + s1) + (s2 + s3));
        }

        __syncthreads();   // (b) STGs + P reads done (WAR + release ordering)

        // ---- announce: this block finished step t ----
        if (tid == 0) red_rel_add(prodflag, 1ull);
    }
}

// ---------------- launch ----------------
extern "C" void kernel_launch(void* const* d_in, const int* in_sizes, int n_in,
                              void* d_out, int out_size)
{
    const float* x  = (const float*)d_in[0];   // [64,512,512]
    const float* h0 = (const float*)d_in[1];   // [64,1024]
    const float* W  = (const float*)d_in[2];   // [512,1024]
    const float* R  = (const float*)d_in[3];   // [1024,1024]
    const float* b  = (const float*)d_in[4];   // [1,1024]
    float* out = (float*)d_out;                // [64,512,1024]

    const int smem_bytes = SMEM_FLOATS * 4;    // 230144 <= 232448
    cudaFuncSetAttribute(rnn_recur_kernel,
                         cudaFuncAttributeMaxDynamicSharedMemorySize, smem_bytes);

    dim3 gX(DIN / 32, MROWS / 32);             // (16, 1024)
    transpose_X<<<gX, dim3(32, 8)>>>(x);

    dim3 gridA(DH / 128, MROWS / 128);         // (8, 256)
    gemm_xw_v3<<<gridA, 256>>>(W, b, out);

    rnn_recur_kernel<<<128, TPB, smem_bytes>>>(h0, R, out);
}